// round 9
// baseline (speedup 1.0000x reference)
#include <cuda_runtime.h>
#include <math.h>

#define NN 100000
#define HH 128
#define EE_MAX 400000
#define GG 256

typedef unsigned long long u64;

// ---------------- static device scratch (no allocations allowed) ----------------
__device__ float d_h[NN * HH];
__device__ float d_vp[NN * HH];
__device__ float d_vl[NN * HH];
__device__ float d_aggi[NN * HH];
__device__ float d_agge[NN * HH];
__device__ float d_cnti[NN];
__device__ float d_cnte[NN];
__device__ float d_winter[EE_MAX];
__device__ float d_gpool[GG * HH];

// ---------------- small helpers ----------------
__device__ __forceinline__ float silu_f(float x) {
    return x / (1.0f + __expf(-x));
}

__device__ __forceinline__ u64 pack2(float v) {
    u64 r;
    asm("mov.b64 %0, {%1, %1};" : "=l"(r) : "f"(v));
    return r;
}

__device__ __forceinline__ u64 fma2(u64 a, u64 b, u64 c) {
    u64 d;
    asm("fma.rn.f32x2 %0, %1, %2, %3;" : "=l"(d) : "l"(a), "l"(b), "l"(c));
    return d;
}

__device__ __forceinline__ float2 unpack2(u64 v) {
    float2 r;
    asm("mov.b64 {%0, %1}, %2;" : "=f"(r.x), "=f"(r.y) : "l"(v));
    return r;
}

// ---------------- zero scratch ----------------
__global__ void zero_kernel() {
    long long i = (long long)blockIdx.x * blockDim.x + threadIdx.x;
    const long long n4 = (long long)NN * HH / 4;
    float4 z = make_float4(0.f, 0.f, 0.f, 0.f);
    if (i < n4) {
        ((float4*)d_vp)[i] = z;
        ((float4*)d_vl)[i] = z;
        ((float4*)d_aggi)[i] = z;
        ((float4*)d_agge)[i] = z;
    }
    if (i < NN) { d_cnti[i] = 0.f; d_cnte[i] = 0.f; }
    if (i < GG * HH) d_gpool[i] = 0.f;
}

// ---------------- node embedding: h = silu(x @ W + b) ----------------
__global__ void embed_kernel(const float* __restrict__ x,
                             const float* __restrict__ W,
                             const float* __restrict__ b, int N) {
    __shared__ float sW[35 * HH];
    __shared__ float sx[64 * 35];
    __shared__ float sb[HH];
    int tid = threadIdx.x;           // 128 threads
    int n0 = blockIdx.x * 64;
    for (int i = tid; i < 35 * HH; i += 128) sW[i] = W[i];
    sb[tid] = b[tid];
    int cnt = min(64, N - n0);
    for (int i = tid; i < cnt * 35; i += 128) sx[i] = x[(long long)n0 * 35 + i];
    __syncthreads();
    int c = tid;
    for (int i = 0; i < cnt; i++) {
        float acc = sb[c];
#pragma unroll
        for (int k = 0; k < 35; k++) acc += sx[i * 35 + k] * sW[k * HH + c];
        d_h[(long long)(n0 + i) * HH + c] = silu_f(acc);
    }
}

// ---------------- degrees + inter-edge geometric weight ----------------
__global__ void prep_kernel(const int* __restrict__ dstI, int Ei,
                            const int* __restrict__ srcE,
                            const int* __restrict__ dstE, int Ee,
                            const float* __restrict__ pos) {
    int i = blockIdx.x * blockDim.x + threadIdx.x;
    if (i < Ei) atomicAdd(&d_cnti[dstI[i]], 1.0f);
    if (i < Ee) {
        int s = srcE[i], d = dstE[i];
        atomicAdd(&d_cnte[d], 1.0f);
        float dx = pos[3 * s + 0] - pos[3 * d + 0];
        float dy = pos[3 * s + 1] - pos[3 * d + 1];
        float dz = pos[3 * s + 2] - pos[3 * d + 2];
        d_winter[i] = expf(-(dx * dx + dy * dy + dz * dz));
    }
}

// ---------------- edge scatter: agg[dst] += h[src] * w[e]  (warp per edge) ----------------
__global__ void scatter_kernel(const int* __restrict__ src,
                               const int* __restrict__ dst,
                               const float* __restrict__ w_in,
                               int which,   // 0 = intra (w_in), 1 = inter (d_winter)
                               int E) {
    int gid = blockIdx.x * blockDim.x + threadIdx.x;
    int e = gid >> 5;
    if (e >= E) return;
    int lane = gid & 31;
    int s = __ldg(&src[e]);
    int d = __ldg(&dst[e]);
    float ww = which ? d_winter[e] : __ldg(&w_in[e]);
    const float4* hv = (const float4*)(d_h + (long long)s * HH);
    float4 v = hv[lane];
    v.x *= ww; v.y *= ww; v.z *= ww; v.w *= ww;
    float* agg = which ? d_agge : d_aggi;
    float* dp = agg + (long long)d * HH + lane * 4;
    asm volatile("red.global.add.v4.f32 [%0], {%1,%2,%3,%4};"
                 :: "l"(dp), "f"(v.x), "f"(v.y), "f"(v.z), "f"(v.w)
                 : "memory");
}

// ---------------- fused dual-GEMM + layer update ----------------
// m_i = (aggi @ W1 + cnt_i*b1) / (cnt_i + 1)
// m_e = (agge @ W2 + cnt_e*b2) * log(cnt_e + 1)
// v_p = silu(m_i + v_p); v_l = silu(m_e + v_l); h += v_p + v_l
__device__ __forceinline__ void load_tiles(const float* __restrict__ Wg,
                                           float* __restrict__ Ag,
                                           float* sW, float* sA,
                                           int tid, int n0, int N) {
    float4* sWv = (float4*)sW;
    const float4* Wv = (const float4*)Wg;
#pragma unroll
    for (int i = 0; i < 16; i++) sWv[tid + i * 256] = Wv[tid + i * 256];
    float4* sAv = (float4*)sA;
    float4* Av = (float4*)(Ag + (size_t)n0 * HH);
    float4 z = make_float4(0.f, 0.f, 0.f, 0.f);
#pragma unroll
    for (int i = 0; i < 8; i++) {
        int idx = tid + i * 256;
        int row = idx >> 5;               // 32 float4 per row
        float4 v = z;
        if (n0 + row < N) { v = Av[idx]; Av[idx] = z; }   // self-zero for next layer
        sAv[idx] = v;
    }
}

__device__ __forceinline__ void gemm_tile(const float* __restrict__ sW,
                                          const float* __restrict__ sA,
                                          int r0, int c0, u64 acc[4][4]) {
#pragma unroll 4
    for (int k = 0; k < HH; k += 4) {
        float4 a[4];
#pragma unroll
        for (int r = 0; r < 4; r++)
            a[r] = *(const float4*)(sA + (r0 + r) * HH + k);
#pragma unroll
        for (int kk = 0; kk < 4; kk++) {
            const ulonglong2* wr = (const ulonglong2*)(sW + (k + kk) * HH + c0);
            ulonglong2 wa = wr[0], wb = wr[1];
#pragma unroll
            for (int r = 0; r < 4; r++) {
                float av = (kk == 0) ? a[r].x : (kk == 1) ? a[r].y
                         : (kk == 2) ? a[r].z : a[r].w;
                u64 ap = pack2(av);
                acc[r][0] = fma2(ap, wa.x, acc[r][0]);
                acc[r][1] = fma2(ap, wa.y, acc[r][1]);
                acc[r][2] = fma2(ap, wb.x, acc[r][2]);
                acc[r][3] = fma2(ap, wb.y, acc[r][3]);
            }
        }
    }
}

#define UPD_SMEM_FLOATS (16384 + 8192 + 256)
#define UPD_SMEM_BYTES (UPD_SMEM_FLOATS * 4)

__global__ void __launch_bounds__(256, 2) update_kernel(
    const float* __restrict__ W1, const float* __restrict__ b1,
    const float* __restrict__ W2, const float* __restrict__ b2, int N) {
    extern __shared__ float sm[];
    float* sW = sm;                 // 16384 floats
    float* sA = sm + 16384;         // 8192 floats
    float* sB1 = sm + 24576;        // 128
    float* sB2 = sm + 24704;        // 128

    int tid = threadIdx.x;          // 256 threads
    int n0 = blockIdx.x * 64;
    if (tid < 128) sB1[tid] = b1[tid];
    else           sB2[tid - 128] = b2[tid - 128];

    const int r0 = (tid >> 4) << 2;       // 16 row groups * 4 rows
    const int c0 = (tid & 15) << 3;       // 16 col groups * 8 cols

    u64 accI[4][4], accE[4][4];
#pragma unroll
    for (int r = 0; r < 4; r++)
#pragma unroll
        for (int p = 0; p < 4; p++) { accI[r][p] = 0ull; accE[r][p] = 0ull; }

    // phase 0: intra
    load_tiles(W1, d_aggi, sW, sA, tid, n0, N);
    __syncthreads();
    gemm_tile(sW, sA, r0, c0, accI);
    __syncthreads();
    // phase 1: inter
    load_tiles(W2, d_agge, sW, sA, tid, n0, N);
    __syncthreads();
    gemm_tile(sW, sA, r0, c0, accE);

    // epilogue
#pragma unroll
    for (int r = 0; r < 4; r++) {
        int n = n0 + r0 + r;
        if (n >= N) break;
        float ci = d_cnti[n], ce = d_cnte[n];
        float inv = 1.0f / (ci + 1.0f);
        float ld = logf(ce + 1.0f);
        long long base = (long long)n * HH + c0;
#pragma unroll
        for (int p = 0; p < 4; p++) {
            float2 mi = unpack2(accI[r][p]);
            float2 me = unpack2(accE[r][p]);
            int c = c0 + 2 * p;
            mi.x = (mi.x + ci * sB1[c])     * inv;
            mi.y = (mi.y + ci * sB1[c + 1]) * inv;
            me.x = (me.x + ce * sB2[c])     * ld;
            me.y = (me.y + ce * sB2[c + 1]) * ld;
            float2 vp = *(float2*)(d_vp + base + 2 * p);
            float2 vl = *(float2*)(d_vl + base + 2 * p);
            float2 hh = *(float2*)(d_h  + base + 2 * p);
            float nvp0 = silu_f(mi.x + vp.x), nvp1 = silu_f(mi.y + vp.y);
            float nvl0 = silu_f(me.x + vl.x), nvl1 = silu_f(me.y + vl.y);
            hh.x += nvp0 + nvl0;
            hh.y += nvp1 + nvl1;
            *(float2*)(d_vp + base + 2 * p) = make_float2(nvp0, nvp1);
            *(float2*)(d_vl + base + 2 * p) = make_float2(nvl0, nvl1);
            *(float2*)(d_h  + base + 2 * p) = hh;
        }
    }
}

// ---------------- global_add_pool (batch is sorted) ----------------
__global__ void pool_kernel(const int* __restrict__ batch, int N) {
    const int NPB = 512;
    __shared__ int sbatch[NPB];
    int n0 = blockIdx.x * NPB;
    int tid = threadIdx.x;            // 128 threads (one per column)
    int cnt = min(NPB, N - n0);
    for (int i = tid; i < cnt; i += 128) sbatch[i] = batch[n0 + i];
    __syncthreads();
    float acc = 0.0f;
    int cur = sbatch[0];
    for (int i = 0; i < cnt; i++) {
        int g = sbatch[i];
        if (g != cur) {
            atomicAdd(&d_gpool[cur * HH + tid], acc);
            acc = 0.0f;
            cur = g;
        }
        acc += d_h[(long long)(n0 + i) * HH + tid];
    }
    atomicAdd(&d_gpool[cur * HH + tid], acc);
}

// ---------------- FC head (one block per graph) ----------------
__global__ void head_kernel(const float* __restrict__ fcW,
                            const float* __restrict__ fcb,
                            const float* __restrict__ gam,
                            const float* __restrict__ bet,
                            const float* __restrict__ outW,
                            const float* __restrict__ outb,
                            float* __restrict__ out) {
    int gr = blockIdx.x;
    int c = threadIdx.x;              // 128 threads
    __shared__ float sg[HH];
    __shared__ float red[4];
    sg[c] = d_gpool[gr * HH + c];
    __syncthreads();
    const float bns = 1.0f / sqrtf(1.0f + 1e-5f);
    for (int j = 0; j < 3; j++) {
        const float* Wj = fcW + j * HH * HH;
        float acc = fcb[j * HH + c];
#pragma unroll 8
        for (int k = 0; k < HH; k++) acc += sg[k] * Wj[k * HH + c];
        acc = acc > 0.0f ? acc : 0.01f * acc;           // leaky_relu
        acc = acc * bns * gam[j * HH + c] + bet[j * HH + c];
        __syncthreads();
        sg[c] = acc;
        __syncthreads();
    }
    float v = sg[c] * outW[c];
#pragma unroll
    for (int o = 16; o > 0; o >>= 1) v += __shfl_xor_sync(0xffffffffu, v, o);
    if ((c & 31) == 0) red[c >> 5] = v;
    __syncthreads();
    if (c == 0) out[gr] = red[0] + red[1] + red[2] + red[3] + outb[0];
}

// ---------------- launch ----------------
extern "C" void kernel_launch(void* const* d_in, const int* in_sizes, int n_in,
                              void* d_out, int out_size) {
    const float* x     = (const float*)d_in[0];
    const int*   eii   = (const int*)d_in[1];
    const int*   eie   = (const int*)d_in[2];
    const float* pos   = (const float*)d_in[3];
    const float* eattr = (const float*)d_in[4];
    const int*   batch = (const int*)d_in[5];
    const float* linW  = (const float*)d_in[6];
    const float* linb  = (const float*)d_in[7];
    const float* Wi    = (const float*)d_in[8];
    const float* bi    = (const float*)d_in[9];
    const float* We    = (const float*)d_in[10];
    const float* be    = (const float*)d_in[11];
    const float* fcW   = (const float*)d_in[12];
    const float* fcb   = (const float*)d_in[13];
    const float* gam   = (const float*)d_in[14];
    const float* bet   = (const float*)d_in[15];
    const float* outW  = (const float*)d_in[16];
    const float* outb  = (const float*)d_in[17];
    float* out = (float*)d_out;

    int N  = in_sizes[5];
    int Ei = in_sizes[4];        // edge_attr has E_INTRA elements
    int Ee = in_sizes[2] / 2;

    const int* srcI = eii;
    const int* dstI = eii + Ei;
    const int* srcE = eie;
    const int* dstE = eie + Ee;

    cudaFuncSetAttribute(update_kernel,
                         cudaFuncAttributeMaxDynamicSharedMemorySize,
                         UPD_SMEM_BYTES);

    zero_kernel<<<(NN * HH / 4 + 255) / 256, 256>>>();
    embed_kernel<<<(N + 63) / 64, 128>>>(x, linW, linb, N);
    int Emax = Ei > Ee ? Ei : Ee;
    prep_kernel<<<(Emax + 255) / 256, 256>>>(dstI, Ei, srcE, dstE, Ee, pos);

    for (int l = 0; l < 4; l++) {
        long long ti = (long long)Ei * 32;
        long long te = (long long)Ee * 32;
        scatter_kernel<<<(int)((ti + 255) / 256), 256>>>(srcI, dstI, eattr, 0, Ei);
        scatter_kernel<<<(int)((te + 255) / 256), 256>>>(srcE, dstE, eattr, 1, Ee);
        update_kernel<<<(N + 63) / 64, 256, UPD_SMEM_BYTES>>>(
            Wi + (size_t)l * HH * HH, bi + (size_t)l * HH,
            We + (size_t)l * HH * HH, be + (size_t)l * HH, N);
    }

    pool_kernel<<<(N + 511) / 512, 128>>>(batch, N);
    head_kernel<<<GG, 128>>>(fcW, fcb, gam, bet, outW, outb, out);
}

// round 10
// speedup vs baseline: 1.0026x; 1.0026x over previous
#include <cuda_runtime.h>
#include <math.h>

#define NN 100000
#define HH 128
#define EE_MAX 400000
#define GG 256

typedef unsigned long long u64;

// ---------------- static device scratch (no allocations allowed) ----------------
__device__ float d_h[NN * HH];
__device__ float d_vp[NN * HH];
__device__ float d_vl[NN * HH];
__device__ float d_aggi[NN * HH];
__device__ float d_agge[NN * HH];
__device__ float d_cnti[NN];
__device__ float d_cnte[NN];
__device__ float d_winter[EE_MAX];
__device__ float d_gpool[GG * HH];

// ---------------- small helpers ----------------
__device__ __forceinline__ float silu_f(float x) {
    return x / (1.0f + __expf(-x));
}

__device__ __forceinline__ u64 pack2(float v) {
    u64 r;
    asm("mov.b64 %0, {%1, %1};" : "=l"(r) : "f"(v));
    return r;
}

__device__ __forceinline__ u64 fma2(u64 a, u64 b, u64 c) {
    u64 d;
    asm("fma.rn.f32x2 %0, %1, %2, %3;" : "=l"(d) : "l"(a), "l"(b), "l"(c));
    return d;
}

__device__ __forceinline__ float2 unpack2(u64 v) {
    float2 r;
    asm("mov.b64 {%0, %1}, %2;" : "=f"(r.x), "=f"(r.y) : "l"(v));
    return r;
}

// ---------------- zero scratch ----------------
__global__ void zero_kernel() {
    long long i = (long long)blockIdx.x * blockDim.x + threadIdx.x;
    const long long n4 = (long long)NN * HH / 4;
    float4 z = make_float4(0.f, 0.f, 0.f, 0.f);
    if (i < n4) {
        ((float4*)d_vp)[i] = z;
        ((float4*)d_vl)[i] = z;
        ((float4*)d_aggi)[i] = z;
        ((float4*)d_agge)[i] = z;
    }
    if (i < NN) { d_cnti[i] = 0.f; d_cnte[i] = 0.f; }
    if (i < GG * HH) d_gpool[i] = 0.f;
}

// ---------------- node embedding: h = silu(x @ W + b) ----------------
__global__ void embed_kernel(const float* __restrict__ x,
                             const float* __restrict__ W,
                             const float* __restrict__ b, int N) {
    __shared__ float sW[35 * HH];
    __shared__ float sx[64 * 35];
    __shared__ float sb[HH];
    int tid = threadIdx.x;           // 128 threads
    int n0 = blockIdx.x * 64;
    for (int i = tid; i < 35 * HH; i += 128) sW[i] = W[i];
    sb[tid] = b[tid];
    int cnt = min(64, N - n0);
    for (int i = tid; i < cnt * 35; i += 128) sx[i] = x[(long long)n0 * 35 + i];
    __syncthreads();
    int c = tid;
    for (int i = 0; i < cnt; i++) {
        float acc = sb[c];
#pragma unroll
        for (int k = 0; k < 35; k++) acc += sx[i * 35 + k] * sW[k * HH + c];
        d_h[(long long)(n0 + i) * HH + c] = silu_f(acc);
    }
}

// ---------------- degrees + inter-edge geometric weight ----------------
__global__ void prep_kernel(const int* __restrict__ dstI, int Ei,
                            const int* __restrict__ srcE,
                            const int* __restrict__ dstE, int Ee,
                            const float* __restrict__ pos) {
    int i = blockIdx.x * blockDim.x + threadIdx.x;
    if (i < Ei) atomicAdd(&d_cnti[dstI[i]], 1.0f);
    if (i < Ee) {
        int s = srcE[i], d = dstE[i];
        atomicAdd(&d_cnte[d], 1.0f);
        float dx = pos[3 * s + 0] - pos[3 * d + 0];
        float dy = pos[3 * s + 1] - pos[3 * d + 1];
        float dz = pos[3 * s + 2] - pos[3 * d + 2];
        d_winter[i] = expf(-(dx * dx + dy * dy + dz * dz));
    }
}

// ---------------- edge scatter: agg[dst] += h[src] * w[e]  (warp per edge) ----------------
__global__ void scatter_kernel(const int* __restrict__ src,
                               const int* __restrict__ dst,
                               const float* __restrict__ w_in,
                               int which,   // 0 = intra (w_in), 1 = inter (d_winter)
                               int E) {
    int gid = blockIdx.x * blockDim.x + threadIdx.x;
    int e = gid >> 5;
    if (e >= E) return;
    int lane = gid & 31;
    int s = __ldg(&src[e]);
    int d = __ldg(&dst[e]);
    float ww = which ? d_winter[e] : __ldg(&w_in[e]);
    const float4* hv = (const float4*)(d_h + (long long)s * HH);
    float4 v = hv[lane];
    v.x *= ww; v.y *= ww; v.z *= ww; v.w *= ww;
    float* agg = which ? d_agge : d_aggi;
    float* dp = agg + (long long)d * HH + lane * 4;
    asm volatile("red.global.add.v4.f32 [%0], {%1,%2,%3,%4};"
                 :: "l"(dp), "f"(v.x), "f"(v.y), "f"(v.z), "f"(v.w)
                 : "memory");
}

// ---------------- fused dual-GEMM + layer update ----------------
// m_i = (aggi @ W1 + cnt_i*b1) / (cnt_i + 1)
// m_e = (agge @ W2 + cnt_e*b2) * log(cnt_e + 1)
// v_p = silu(m_i + v_p); v_l = silu(m_e + v_l); h += v_p + v_l
__device__ __forceinline__ void load_tiles(const float* __restrict__ Wg,
                                           float* __restrict__ Ag,
                                           float* sW, float* sA,
                                           int tid, int n0, int N) {
    float4* sWv = (float4*)sW;
    const float4* Wv = (const float4*)Wg;
#pragma unroll
    for (int i = 0; i < 16; i++) sWv[tid + i * 256] = Wv[tid + i * 256];
    float4* sAv = (float4*)sA;
    float4* Av = (float4*)(Ag + (size_t)n0 * HH);
    float4 z = make_float4(0.f, 0.f, 0.f, 0.f);
#pragma unroll
    for (int i = 0; i < 8; i++) {
        int idx = tid + i * 256;
        int row = idx >> 5;               // 32 float4 per row
        float4 v = z;
        if (n0 + row < N) { v = Av[idx]; Av[idx] = z; }   // self-zero for next layer
        sAv[idx] = v;
    }
}

__device__ __forceinline__ void gemm_tile(const float* __restrict__ sW,
                                          const float* __restrict__ sA,
                                          int r0, int c0, u64 acc[4][4]) {
#pragma unroll 4
    for (int k = 0; k < HH; k += 4) {
        float4 a[4];
#pragma unroll
        for (int r = 0; r < 4; r++)
            a[r] = *(const float4*)(sA + (r0 + r) * HH + k);
#pragma unroll
        for (int kk = 0; kk < 4; kk++) {
            const ulonglong2* wr = (const ulonglong2*)(sW + (k + kk) * HH + c0);
            ulonglong2 wa = wr[0], wb = wr[1];
#pragma unroll
            for (int r = 0; r < 4; r++) {
                float av = (kk == 0) ? a[r].x : (kk == 1) ? a[r].y
                         : (kk == 2) ? a[r].z : a[r].w;
                u64 ap = pack2(av);
                acc[r][0] = fma2(ap, wa.x, acc[r][0]);
                acc[r][1] = fma2(ap, wa.y, acc[r][1]);
                acc[r][2] = fma2(ap, wb.x, acc[r][2]);
                acc[r][3] = fma2(ap, wb.y, acc[r][3]);
            }
        }
    }
}

#define UPD_SMEM_FLOATS (16384 + 8192 + 256)
#define UPD_SMEM_BYTES (UPD_SMEM_FLOATS * 4)

__global__ void __launch_bounds__(256, 2) update_kernel(
    const float* __restrict__ W1, const float* __restrict__ b1,
    const float* __restrict__ W2, const float* __restrict__ b2, int N) {
    extern __shared__ float sm[];
    float* sW = sm;                 // 16384 floats
    float* sA = sm + 16384;         // 8192 floats
    float* sB1 = sm + 24576;        // 128
    float* sB2 = sm + 24704;        // 128

    int tid = threadIdx.x;          // 256 threads
    int n0 = blockIdx.x * 64;
    if (tid < 128) sB1[tid] = b1[tid];
    else           sB2[tid - 128] = b2[tid - 128];

    const int r0 = (tid >> 4) << 2;       // 16 row groups * 4 rows
    const int c0 = (tid & 15) << 3;       // 16 col groups * 8 cols

    u64 accI[4][4], accE[4][4];
#pragma unroll
    for (int r = 0; r < 4; r++)
#pragma unroll
        for (int p = 0; p < 4; p++) { accI[r][p] = 0ull; accE[r][p] = 0ull; }

    // phase 0: intra
    load_tiles(W1, d_aggi, sW, sA, tid, n0, N);
    __syncthreads();
    gemm_tile(sW, sA, r0, c0, accI);
    __syncthreads();
    // phase 1: inter
    load_tiles(W2, d_agge, sW, sA, tid, n0, N);
    __syncthreads();
    gemm_tile(sW, sA, r0, c0, accE);

    // epilogue
#pragma unroll
    for (int r = 0; r < 4; r++) {
        int n = n0 + r0 + r;
        if (n >= N) break;
        float ci = d_cnti[n], ce = d_cnte[n];
        float inv = 1.0f / (ci + 1.0f);
        float ld = logf(ce + 1.0f);
        long long base = (long long)n * HH + c0;
#pragma unroll
        for (int p = 0; p < 4; p++) {
            float2 mi = unpack2(accI[r][p]);
            float2 me = unpack2(accE[r][p]);
            int c = c0 + 2 * p;
            mi.x = (mi.x + ci * sB1[c])     * inv;
            mi.y = (mi.y + ci * sB1[c + 1]) * inv;
            me.x = (me.x + ce * sB2[c])     * ld;
            me.y = (me.y + ce * sB2[c + 1]) * ld;
            float2 vp = *(float2*)(d_vp + base + 2 * p);
            float2 vl = *(float2*)(d_vl + base + 2 * p);
            float2 hh = *(float2*)(d_h  + base + 2 * p);
            float nvp0 = silu_f(mi.x + vp.x), nvp1 = silu_f(mi.y + vp.y);
            float nvl0 = silu_f(me.x + vl.x), nvl1 = silu_f(me.y + vl.y);
            hh.x += nvp0 + nvl0;
            hh.y += nvp1 + nvl1;
            *(float2*)(d_vp + base + 2 * p) = make_float2(nvp0, nvp1);
            *(float2*)(d_vl + base + 2 * p) = make_float2(nvl0, nvl1);
            *(float2*)(d_h  + base + 2 * p) = hh;
        }
    }
}

// ---------------- global_add_pool (batch is sorted) ----------------
__global__ void pool_kernel(const int* __restrict__ batch, int N) {
    const int NPB = 512;
    __shared__ int sbatch[NPB];
    int n0 = blockIdx.x * NPB;
    int tid = threadIdx.x;            // 128 threads (one per column)
    int cnt = min(NPB, N - n0);
    for (int i = tid; i < cnt; i += 128) sbatch[i] = batch[n0 + i];
    __syncthreads();
    float acc = 0.0f;
    int cur = sbatch[0];
    for (int i = 0; i < cnt; i++) {
        int g = sbatch[i];
        if (g != cur) {
            atomicAdd(&d_gpool[cur * HH + tid], acc);
            acc = 0.0f;
            cur = g;
        }
        acc += d_h[(long long)(n0 + i) * HH + tid];
    }
    atomicAdd(&d_gpool[cur * HH + tid], acc);
}

// ---------------- FC head (one block per graph) ----------------
__global__ void head_kernel(const float* __restrict__ fcW,
                            const float* __restrict__ fcb,
                            const float* __restrict__ gam,
                            const float* __restrict__ bet,
                            const float* __restrict__ outW,
                            const float* __restrict__ outb,
                            float* __restrict__ out) {
    int gr = blockIdx.x;
    int c = threadIdx.x;              // 128 threads
    __shared__ float sg[HH];
    __shared__ float red[4];
    sg[c] = d_gpool[gr * HH + c];
    __syncthreads();
    const float bns = 1.0f / sqrtf(1.0f + 1e-5f);
    for (int j = 0; j < 3; j++) {
        const float* Wj = fcW + j * HH * HH;
        float acc = fcb[j * HH + c];
#pragma unroll 8
        for (int k = 0; k < HH; k++) acc += sg[k] * Wj[k * HH + c];
        acc = acc > 0.0f ? acc : 0.01f * acc;           // leaky_relu
        acc = acc * bns * gam[j * HH + c] + bet[j * HH + c];
        __syncthreads();
        sg[c] = acc;
        __syncthreads();
    }
    float v = sg[c] * outW[c];
#pragma unroll
    for (int o = 16; o > 0; o >>= 1) v += __shfl_xor_sync(0xffffffffu, v, o);
    if ((c & 31) == 0) red[c >> 5] = v;
    __syncthreads();
    if (c == 0) out[gr] = red[0] + red[1] + red[2] + red[3] + outb[0];
}

// ---------------- launch ----------------
extern "C" void kernel_launch(void* const* d_in, const int* in_sizes, int n_in,
                              void* d_out, int out_size) {
    const float* x     = (const float*)d_in[0];
    const int*   eii   = (const int*)d_in[1];
    const int*   eie   = (const int*)d_in[2];
    const float* pos   = (const float*)d_in[3];
    const float* eattr = (const float*)d_in[4];
    const int*   batch = (const int*)d_in[5];
    const float* linW  = (const float*)d_in[6];
    const float* linb  = (const float*)d_in[7];
    const float* Wi    = (const float*)d_in[8];
    const float* bi    = (const float*)d_in[9];
    const float* We    = (const float*)d_in[10];
    const float* be    = (const float*)d_in[11];
    const float* fcW   = (const float*)d_in[12];
    const float* fcb   = (const float*)d_in[13];
    const float* gam   = (const float*)d_in[14];
    const float* bet   = (const float*)d_in[15];
    const float* outW  = (const float*)d_in[16];
    const float* outb  = (const float*)d_in[17];
    float* out = (float*)d_out;

    int N  = in_sizes[5];
    int Ei = in_sizes[4];        // edge_attr has E_INTRA elements
    int Ee = in_sizes[2] / 2;

    const int* srcI = eii;
    const int* dstI = eii + Ei;
    const int* srcE = eie;
    const int* dstE = eie + Ee;

    cudaFuncSetAttribute(update_kernel,
                         cudaFuncAttributeMaxDynamicSharedMemorySize,
                         UPD_SMEM_BYTES);

    zero_kernel<<<(NN * HH / 4 + 255) / 256, 256>>>();
    embed_kernel<<<(N + 63) / 64, 128>>>(x, linW, linb, N);
    int Emax = Ei > Ee ? Ei : Ee;
    prep_kernel<<<(Emax + 255) / 256, 256>>>(dstI, Ei, srcE, dstE, Ee, pos);

    for (int l = 0; l < 4; l++) {
        long long ti = (long long)Ei * 32;
        long long te = (long long)Ee * 32;
        scatter_kernel<<<(int)((ti + 255) / 256), 256>>>(srcI, dstI, eattr, 0, Ei);
        scatter_kernel<<<(int)((te + 255) / 256), 256>>>(srcE, dstE, eattr, 1, Ee);
        update_kernel<<<(N + 63) / 64, 256, UPD_SMEM_BYTES>>>(
            Wi + (size_t)l * HH * HH, bi + (size_t)l * HH,
            We + (size_t)l * HH * HH, be + (size_t)l * HH, N);
    }

    pool_kernel<<<(N + 511) / 512, 128>>>(batch, N);
    head_kernel<<<GG, 128>>>(fcW, fcb, gam, bet, outW, outb, out);
}

// round 11
// speedup vs baseline: 1.2700x; 1.2667x over previous
#include <cuda_runtime.h>
#include <math.h>

#define NN 100000
#define HH 128
#define EI_MAX 800000
#define EE_MAX 400000
#define GG 256

typedef unsigned long long u64;

// ---------------- static device scratch (no allocations allowed) ----------------
__device__ float d_h0[NN * HH];
__device__ float d_h1[NN * HH];
__device__ float d_vp[NN * HH];
__device__ float d_vl[NN * HH];
__device__ int   d_degI[NN], d_degE[NN];
__device__ int   d_rowI[NN], d_rowE[NN];
__device__ int   d_curI[NN], d_curE[NN];
__device__ int   d_totI, d_totE;
__device__ int2  d_pairI[EI_MAX];   // {src, weight-as-int-bits}
__device__ int2  d_pairE[EE_MAX];
__device__ float d_gpool[GG * HH];

// ---------------- small helpers ----------------
__device__ __forceinline__ float silu_f(float x) {
    return x / (1.0f + __expf(-x));
}

__device__ __forceinline__ u64 pack2(float v) {
    u64 r;
    asm("mov.b64 %0, {%1, %1};" : "=l"(r) : "f"(v));
    return r;
}

__device__ __forceinline__ u64 fma2(u64 a, u64 b, u64 c) {
    u64 d;
    asm("fma.rn.f32x2 %0, %1, %2, %3;" : "=l"(d) : "l"(a), "l"(b), "l"(c));
    return d;
}

__device__ __forceinline__ float2 unpack2(u64 v) {
    float2 r;
    asm("mov.b64 {%0, %1}, %2;" : "=f"(r.x), "=f"(r.y) : "l"(v));
    return r;
}

// ---------------- zero scratch ----------------
__global__ void zero_kernel() {
    long long i = (long long)blockIdx.x * blockDim.x + threadIdx.x;
    const long long n4 = (long long)NN * HH / 4;
    float4 z = make_float4(0.f, 0.f, 0.f, 0.f);
    if (i < n4) {
        ((float4*)d_vp)[i] = z;
        ((float4*)d_vl)[i] = z;
    }
    if (i < NN) { d_degI[i] = 0; d_degE[i] = 0; }
    if (i < GG * HH) d_gpool[i] = 0.f;
    if (i == 0) { d_totI = 0; d_totE = 0; }
}

// ---------------- node embedding: h = silu(x @ W + b) ----------------
__global__ void embed_kernel(const float* __restrict__ x,
                             const float* __restrict__ W,
                             const float* __restrict__ b, int N) {
    __shared__ float sW[35 * HH];
    __shared__ float sx[64 * 35];
    __shared__ float sb[HH];
    int tid = threadIdx.x;           // 128 threads
    int n0 = blockIdx.x * 64;
    for (int i = tid; i < 35 * HH; i += 128) sW[i] = W[i];
    sb[tid] = b[tid];
    int cnt = min(64, N - n0);
    for (int i = tid; i < cnt * 35; i += 128) sx[i] = x[(long long)n0 * 35 + i];
    __syncthreads();
    int c = tid;
    for (int i = 0; i < cnt; i++) {
        float acc = sb[c];
#pragma unroll
        for (int k = 0; k < 35; k++) acc += sx[i * 35 + k] * sW[k * HH + c];
        d_h0[(long long)(n0 + i) * HH + c] = silu_f(acc);
    }
}

// ---------------- CSR build: count, alloc (warp-aggregated), fill ----------------
__global__ void count_kernel(const int* __restrict__ dstI, int Ei,
                             const int* __restrict__ dstE, int Ee) {
    int i = blockIdx.x * blockDim.x + threadIdx.x;
    if (i < Ei) atomicAdd(&d_degI[dstI[i]], 1);
    if (i < Ee) atomicAdd(&d_degE[dstE[i]], 1);
}

__global__ void alloc_kernel(int N) {
    int n = blockIdx.x * blockDim.x + threadIdx.x;
    int lane = threadIdx.x & 31;
    int di = (n < N) ? d_degI[n] : 0;
    int de = (n < N) ? d_degE[n] : 0;
    int si = di, se = de;
#pragma unroll
    for (int o = 1; o < 32; o <<= 1) {
        int ti = __shfl_up_sync(0xffffffffu, si, o);
        int te = __shfl_up_sync(0xffffffffu, se, o);
        if (lane >= o) { si += ti; se += te; }
    }
    int baseI = 0, baseE = 0;
    if (lane == 31) {
        baseI = atomicAdd(&d_totI, si);
        baseE = atomicAdd(&d_totE, se);
    }
    baseI = __shfl_sync(0xffffffffu, baseI, 31);
    baseE = __shfl_sync(0xffffffffu, baseE, 31);
    if (n < N) {
        int sI = baseI + si - di;     // exclusive within warp
        int sE = baseE + se - de;
        d_rowI[n] = sI; d_curI[n] = sI;
        d_rowE[n] = sE; d_curE[n] = sE;
    }
}

__global__ void fill_kernel(const int* __restrict__ srcI,
                            const int* __restrict__ dstI,
                            const float* __restrict__ eattr, int Ei,
                            const int* __restrict__ srcE,
                            const int* __restrict__ dstE,
                            const float* __restrict__ pos, int Ee) {
    int i = blockIdx.x * blockDim.x + threadIdx.x;
    if (i < Ei) {
        int d = dstI[i];
        int slot = atomicAdd(&d_curI[d], 1);
        d_pairI[slot] = make_int2(srcI[i], __float_as_int(eattr[i]));
    }
    if (i < Ee) {
        int s = srcE[i], d = dstE[i];
        int slot = atomicAdd(&d_curE[d], 1);
        float dx = pos[3 * s + 0] - pos[3 * d + 0];
        float dy = pos[3 * s + 1] - pos[3 * d + 1];
        float dz = pos[3 * s + 2] - pos[3 * d + 2];
        float w = expf(-(dx * dx + dy * dy + dz * dz));
        d_pairE[slot] = make_int2(s, __float_as_int(w));
    }
}

// ---------------- fused layer: CSR gather -> dual GEMM -> update ----------------
__device__ __forceinline__ float4 gather_row(const float* __restrict__ h_in,
                                             const int2* __restrict__ pairs,
                                             int s0, int dg, int lane) {
    float4 acc = make_float4(0.f, 0.f, 0.f, 0.f);
    int j = 0;
    for (; j + 4 <= dg; j += 4) {
        int2 p0 = __ldg(&pairs[s0 + j + 0]);
        int2 p1 = __ldg(&pairs[s0 + j + 1]);
        int2 p2 = __ldg(&pairs[s0 + j + 2]);
        int2 p3 = __ldg(&pairs[s0 + j + 3]);
        float4 v0 = __ldg((const float4*)(h_in + (size_t)p0.x * HH) + lane);
        float4 v1 = __ldg((const float4*)(h_in + (size_t)p1.x * HH) + lane);
        float4 v2 = __ldg((const float4*)(h_in + (size_t)p2.x * HH) + lane);
        float4 v3 = __ldg((const float4*)(h_in + (size_t)p3.x * HH) + lane);
        float w0 = __int_as_float(p0.y), w1 = __int_as_float(p1.y);
        float w2 = __int_as_float(p2.y), w3 = __int_as_float(p3.y);
        acc.x = fmaf(v0.x, w0, acc.x); acc.y = fmaf(v0.y, w0, acc.y);
        acc.z = fmaf(v0.z, w0, acc.z); acc.w = fmaf(v0.w, w0, acc.w);
        acc.x = fmaf(v1.x, w1, acc.x); acc.y = fmaf(v1.y, w1, acc.y);
        acc.z = fmaf(v1.z, w1, acc.z); acc.w = fmaf(v1.w, w1, acc.w);
        acc.x = fmaf(v2.x, w2, acc.x); acc.y = fmaf(v2.y, w2, acc.y);
        acc.z = fmaf(v2.z, w2, acc.z); acc.w = fmaf(v2.w, w2, acc.w);
        acc.x = fmaf(v3.x, w3, acc.x); acc.y = fmaf(v3.y, w3, acc.y);
        acc.z = fmaf(v3.z, w3, acc.z); acc.w = fmaf(v3.w, w3, acc.w);
    }
    for (; j < dg; j++) {
        int2 p = __ldg(&pairs[s0 + j]);
        float4 v = __ldg((const float4*)(h_in + (size_t)p.x * HH) + lane);
        float w = __int_as_float(p.y);
        acc.x = fmaf(v.x, w, acc.x); acc.y = fmaf(v.y, w, acc.y);
        acc.z = fmaf(v.z, w, acc.z); acc.w = fmaf(v.w, w, acc.w);
    }
    return acc;
}

__device__ __forceinline__ void gather_tile(const float* __restrict__ h_in,
                                            const int2* __restrict__ pairs,
                                            const int* __restrict__ rowp,
                                            const int* __restrict__ deg,
                                            float* __restrict__ sA,
                                            int n0, int N, int tid) {
    int warp = tid >> 5, lane = tid & 31;
#pragma unroll
    for (int r = 0; r < 8; r++) {
        int row = warp * 8 + r;
        int n = n0 + row;
        float4 acc = make_float4(0.f, 0.f, 0.f, 0.f);
        if (n < N) {
            int s0 = __ldg(&rowp[n]);
            int dg = __ldg(&deg[n]);
            acc = gather_row(h_in, pairs, s0, dg, lane);
        }
        *(float4*)(sA + row * HH + lane * 4) = acc;
    }
}

__device__ __forceinline__ void load_W(const float* __restrict__ Wg,
                                       float* __restrict__ sW, int tid) {
    float4* sWv = (float4*)sW;
    const float4* Wv = (const float4*)Wg;
#pragma unroll
    for (int i = 0; i < 16; i++) sWv[tid + i * 256] = __ldg(&Wv[tid + i * 256]);
}

__device__ __forceinline__ void gemm_tile(const float* __restrict__ sW,
                                          const float* __restrict__ sA,
                                          int r0, int c0, u64 acc[4][4]) {
#pragma unroll 4
    for (int k = 0; k < HH; k += 4) {
        float4 a[4];
#pragma unroll
        for (int r = 0; r < 4; r++)
            a[r] = *(const float4*)(sA + (r0 + r) * HH + k);
#pragma unroll
        for (int kk = 0; kk < 4; kk++) {
            const ulonglong2* wr = (const ulonglong2*)(sW + (k + kk) * HH + c0);
            ulonglong2 wa = wr[0], wb = wr[1];
#pragma unroll
            for (int r = 0; r < 4; r++) {
                float av = (kk == 0) ? a[r].x : (kk == 1) ? a[r].y
                         : (kk == 2) ? a[r].z : a[r].w;
                u64 ap = pack2(av);
                acc[r][0] = fma2(ap, wa.x, acc[r][0]);
                acc[r][1] = fma2(ap, wa.y, acc[r][1]);
                acc[r][2] = fma2(ap, wb.x, acc[r][2]);
                acc[r][3] = fma2(ap, wb.y, acc[r][3]);
            }
        }
    }
}

#define UPD_SMEM_FLOATS (16384 + 8192 + 256)
#define UPD_SMEM_BYTES (UPD_SMEM_FLOATS * 4)

__global__ void __launch_bounds__(256, 2) layer_kernel(
    const float* __restrict__ h_in, float* __restrict__ h_out,
    const float* __restrict__ W1, const float* __restrict__ b1,
    const float* __restrict__ W2, const float* __restrict__ b2, int N) {
    extern __shared__ float sm[];
    float* sW = sm;                 // 16384 floats
    float* sA = sm + 16384;         // 8192 floats
    float* sB1 = sm + 24576;        // 128
    float* sB2 = sm + 24704;        // 128

    int tid = threadIdx.x;          // 256 threads
    int n0 = blockIdx.x * 64;
    if (tid < 128) sB1[tid] = b1[tid];
    else           sB2[tid - 128] = b2[tid - 128];

    const int r0 = (tid >> 4) << 2;       // 16 row groups * 4 rows
    const int c0 = (tid & 15) << 3;       // 16 col groups * 8 cols

    u64 accI[4][4], accE[4][4];
#pragma unroll
    for (int r = 0; r < 4; r++)
#pragma unroll
        for (int p = 0; p < 4; p++) { accI[r][p] = 0ull; accE[r][p] = 0ull; }

    // phase A: intra
    load_W(W1, sW, tid);
    gather_tile(h_in, d_pairI, d_rowI, d_degI, sA, n0, N, tid);
    __syncthreads();
    gemm_tile(sW, sA, r0, c0, accI);
    __syncthreads();
    // phase B: inter
    load_W(W2, sW, tid);
    gather_tile(h_in, d_pairE, d_rowE, d_degE, sA, n0, N, tid);
    __syncthreads();
    gemm_tile(sW, sA, r0, c0, accE);

    // epilogue
#pragma unroll
    for (int r = 0; r < 4; r++) {
        int n = n0 + r0 + r;
        if (n >= N) break;
        float ci = (float)__ldg(&d_degI[n]);
        float ce = (float)__ldg(&d_degE[n]);
        float inv = 1.0f / (ci + 1.0f);
        float ld = logf(ce + 1.0f);
        long long base = (long long)n * HH + c0;
#pragma unroll
        for (int p = 0; p < 4; p++) {
            float2 mi = unpack2(accI[r][p]);
            float2 me = unpack2(accE[r][p]);
            int c = c0 + 2 * p;
            mi.x = (mi.x + ci * sB1[c])     * inv;
            mi.y = (mi.y + ci * sB1[c + 1]) * inv;
            me.x = (me.x + ce * sB2[c])     * ld;
            me.y = (me.y + ce * sB2[c + 1]) * ld;
            float2 vp = *(float2*)(d_vp + base + 2 * p);
            float2 vl = *(float2*)(d_vl + base + 2 * p);
            float2 hh = *(const float2*)(h_in + base + 2 * p);
            float nvp0 = silu_f(mi.x + vp.x), nvp1 = silu_f(mi.y + vp.y);
            float nvl0 = silu_f(me.x + vl.x), nvl1 = silu_f(me.y + vl.y);
            hh.x += nvp0 + nvl0;
            hh.y += nvp1 + nvl1;
            *(float2*)(d_vp + base + 2 * p) = make_float2(nvp0, nvp1);
            *(float2*)(d_vl + base + 2 * p) = make_float2(nvl0, nvl1);
            *(float2*)(h_out + base + 2 * p) = hh;
        }
    }
}

// ---------------- global_add_pool (batch is sorted) ----------------
__global__ void pool_kernel(const float* __restrict__ h,
                            const int* __restrict__ batch, int N) {
    const int NPB = 512;
    __shared__ int sbatch[NPB];
    int n0 = blockIdx.x * NPB;
    int tid = threadIdx.x;            // 128 threads (one per column)
    int cnt = min(NPB, N - n0);
    for (int i = tid; i < cnt; i += 128) sbatch[i] = batch[n0 + i];
    __syncthreads();
    float acc = 0.0f;
    int cur = sbatch[0];
    for (int i = 0; i < cnt; i++) {
        int g = sbatch[i];
        if (g != cur) {
            atomicAdd(&d_gpool[cur * HH + tid], acc);
            acc = 0.0f;
            cur = g;
        }
        acc += h[(long long)(n0 + i) * HH + tid];
    }
    atomicAdd(&d_gpool[cur * HH + tid], acc);
}

// ---------------- FC head (one block per graph) ----------------
__global__ void head_kernel(const float* __restrict__ fcW,
                            const float* __restrict__ fcb,
                            const float* __restrict__ gam,
                            const float* __restrict__ bet,
                            const float* __restrict__ outW,
                            const float* __restrict__ outb,
                            float* __restrict__ out) {
    int gr = blockIdx.x;
    int c = threadIdx.x;              // 128 threads
    __shared__ float sg[HH];
    __shared__ float red[4];
    sg[c] = d_gpool[gr * HH + c];
    __syncthreads();
    const float bns = 1.0f / sqrtf(1.0f + 1e-5f);
    for (int j = 0; j < 3; j++) {
        const float* Wj = fcW + j * HH * HH;
        float acc = fcb[j * HH + c];
#pragma unroll 8
        for (int k = 0; k < HH; k++) acc += sg[k] * Wj[k * HH + c];
        acc = acc > 0.0f ? acc : 0.01f * acc;           // leaky_relu
        acc = acc * bns * gam[j * HH + c] + bet[j * HH + c];
        __syncthreads();
        sg[c] = acc;
        __syncthreads();
    }
    float v = sg[c] * outW[c];
#pragma unroll
    for (int o = 16; o > 0; o >>= 1) v += __shfl_xor_sync(0xffffffffu, v, o);
    if ((c & 31) == 0) red[c >> 5] = v;
    __syncthreads();
    if (c == 0) out[gr] = red[0] + red[1] + red[2] + red[3] + outb[0];
}

// ---------------- launch ----------------
extern "C" void kernel_launch(void* const* d_in, const int* in_sizes, int n_in,
                              void* d_out, int out_size) {
    const float* x     = (const float*)d_in[0];
    const int*   eii   = (const int*)d_in[1];
    const int*   eie   = (const int*)d_in[2];
    const float* pos   = (const float*)d_in[3];
    const float* eattr = (const float*)d_in[4];
    const int*   batch = (const int*)d_in[5];
    const float* linW  = (const float*)d_in[6];
    const float* linb  = (const float*)d_in[7];
    const float* Wi    = (const float*)d_in[8];
    const float* bi    = (const float*)d_in[9];
    const float* We    = (const float*)d_in[10];
    const float* be    = (const float*)d_in[11];
    const float* fcW   = (const float*)d_in[12];
    const float* fcb   = (const float*)d_in[13];
    const float* gam   = (const float*)d_in[14];
    const float* bet   = (const float*)d_in[15];
    const float* outW  = (const float*)d_in[16];
    const float* outb  = (const float*)d_in[17];
    float* out = (float*)d_out;

    int N  = in_sizes[5];
    int Ei = in_sizes[4];        // edge_attr has E_INTRA elements
    int Ee = in_sizes[2] / 2;

    const int* srcI = eii;
    const int* dstI = eii + Ei;
    const int* srcE = eie;
    const int* dstE = eie + Ee;

    cudaFuncSetAttribute(layer_kernel,
                         cudaFuncAttributeMaxDynamicSharedMemorySize,
                         UPD_SMEM_BYTES);

    zero_kernel<<<(NN * HH / 4 + 255) / 256, 256>>>();
    embed_kernel<<<(N + 63) / 64, 128>>>(x, linW, linb, N);

    int Emax = Ei > Ee ? Ei : Ee;
    count_kernel<<<(Emax + 255) / 256, 256>>>(dstI, Ei, dstE, Ee);
    alloc_kernel<<<(N + 255) / 256, 256>>>(N);
    fill_kernel<<<(Emax + 255) / 256, 256>>>(srcI, dstI, eattr, Ei,
                                             srcE, dstE, pos, Ee);

    float* hbuf[2] = { d_h0, d_h1 };
    // resolve device symbol addresses is not allowed at capture time via API;
    // use a small trampoline: pass via kernel pointer arguments using the
    // __device__ arrays directly through a helper kernel is unnecessary —
    // we can take their addresses in device code only. Instead, ping-pong
    // by passing symbol-derived pointers obtained statically:
    // (cudaGetSymbolAddress is host API, allowed outside capture rules? It is
    //  not a stream op; but to stay safe we hard-wire via launches below.)
    (void)hbuf;

    for (int l = 0; l < 4; l++) {
        // even layers: h0 -> h1, odd layers: h1 -> h0
        // device-symbol pointers are resolved inside a tiny wrapper below.
        extern __global__ void layer_wrap(int even, const float*, const float*,
                                          const float*, const float*, int);
        // (fallthrough — actual launch below)
        break;
    }

    // Direct launches with symbol addresses taken via device lambdas are not
    // possible from host; instead use cudaGetSymbolAddress once per call
    // (host-side API, not a memory allocation, not a stream operation).
    static float* p_h0 = nullptr;
    static float* p_h1 = nullptr;
    if (!p_h0) {
        cudaGetSymbolAddress((void**)&p_h0, d_h0);
        cudaGetSymbolAddress((void**)&p_h1, d_h1);
    }

    for (int l = 0; l < 4; l++) {
        const float* hin  = (l & 1) ? p_h1 : p_h0;
        float*       hout = (l & 1) ? p_h0 : p_h1;
        layer_kernel<<<(N + 63) / 64, 256, UPD_SMEM_BYTES>>>(
            hin, hout,
            Wi + (size_t)l * HH * HH, bi + (size_t)l * HH,
            We + (size_t)l * HH * HH, be + (size_t)l * HH, N);
    }

    pool_kernel<<<(N + 511) / 512, 128>>>(p_h0, batch, N);
    head_kernel<<<GG, 128>>>(fcW, fcb, gam, bet, outW, outb, out);
}

// round 12
// speedup vs baseline: 1.2719x; 1.0015x over previous
#include <cuda_runtime.h>
#include <math.h>

#define NN 100000
#define HH 128
#define EI_MAX 800000
#define EE_MAX 400000
#define GG 256

typedef unsigned long long u64;

// ---------------- static device scratch (no allocations allowed) ----------------
__device__ float d_h0[NN * HH];
__device__ float d_h1[NN * HH];
__device__ float d_vp[NN * HH];
__device__ float d_vl[NN * HH];
__device__ int   d_degI[NN], d_degE[NN];
__device__ int   d_rowI[NN], d_rowE[NN];
__device__ int   d_curI[NN], d_curE[NN];
__device__ int   d_totI, d_totE;
__device__ int2  d_pairI[EI_MAX];   // {src, weight-as-int-bits}
__device__ int2  d_pairE[EE_MAX];
__device__ float d_gpool[GG * HH];

// ---------------- small helpers ----------------
__device__ __forceinline__ float silu_f(float x) {
    return x / (1.0f + __expf(-x));
}

__device__ __forceinline__ u64 pack2(float v) {
    u64 r;
    asm("mov.b64 %0, {%1, %1};" : "=l"(r) : "f"(v));
    return r;
}

__device__ __forceinline__ u64 fma2(u64 a, u64 b, u64 c) {
    u64 d;
    asm("fma.rn.f32x2 %0, %1, %2, %3;" : "=l"(d) : "l"(a), "l"(b), "l"(c));
    return d;
}

__device__ __forceinline__ float2 unpack2(u64 v) {
    float2 r;
    asm("mov.b64 {%0, %1}, %2;" : "=f"(r.x), "=f"(r.y) : "l"(v));
    return r;
}

// ---------------- zero scratch ----------------
__global__ void zero_kernel() {
    long long i = (long long)blockIdx.x * blockDim.x + threadIdx.x;
    const long long n4 = (long long)NN * HH / 4;
    float4 z = make_float4(0.f, 0.f, 0.f, 0.f);
    if (i < n4) {
        ((float4*)d_vp)[i] = z;
        ((float4*)d_vl)[i] = z;
    }
    if (i < NN) { d_degI[i] = 0; d_degE[i] = 0; }
    if (i < GG * HH) d_gpool[i] = 0.f;
    if (i == 0) { d_totI = 0; d_totE = 0; }
}

// ---------------- node embedding: h = silu(x @ W + b) ----------------
__global__ void embed_kernel(const float* __restrict__ x,
                             const float* __restrict__ W,
                             const float* __restrict__ b, int N) {
    __shared__ float sW[35 * HH];
    __shared__ float sx[64 * 35];
    __shared__ float sb[HH];
    int tid = threadIdx.x;           // 128 threads
    int n0 = blockIdx.x * 64;
    for (int i = tid; i < 35 * HH; i += 128) sW[i] = W[i];
    sb[tid] = b[tid];
    int cnt = min(64, N - n0);
    for (int i = tid; i < cnt * 35; i += 128) sx[i] = x[(long long)n0 * 35 + i];
    __syncthreads();
    int c = tid;
    for (int i = 0; i < cnt; i++) {
        float acc = sb[c];
#pragma unroll
        for (int k = 0; k < 35; k++) acc += sx[i * 35 + k] * sW[k * HH + c];
        d_h0[(long long)(n0 + i) * HH + c] = silu_f(acc);
    }
}

// ---------------- CSR build: count, alloc (warp-aggregated), fill ----------------
__global__ void count_kernel(const int* __restrict__ dstI, int Ei,
                             const int* __restrict__ dstE, int Ee) {
    int i = blockIdx.x * blockDim.x + threadIdx.x;
    if (i < Ei) atomicAdd(&d_degI[dstI[i]], 1);
    if (i < Ee) atomicAdd(&d_degE[dstE[i]], 1);
}

__global__ void alloc_kernel(int N) {
    int n = blockIdx.x * blockDim.x + threadIdx.x;
    int lane = threadIdx.x & 31;
    int di = (n < N) ? d_degI[n] : 0;
    int de = (n < N) ? d_degE[n] : 0;
    int si = di, se = de;
#pragma unroll
    for (int o = 1; o < 32; o <<= 1) {
        int ti = __shfl_up_sync(0xffffffffu, si, o);
        int te = __shfl_up_sync(0xffffffffu, se, o);
        if (lane >= o) { si += ti; se += te; }
    }
    int baseI = 0, baseE = 0;
    if (lane == 31) {
        baseI = atomicAdd(&d_totI, si);
        baseE = atomicAdd(&d_totE, se);
    }
    baseI = __shfl_sync(0xffffffffu, baseI, 31);
    baseE = __shfl_sync(0xffffffffu, baseE, 31);
    if (n < N) {
        int sI = baseI + si - di;     // exclusive within warp
        int sE = baseE + se - de;
        d_rowI[n] = sI; d_curI[n] = sI;
        d_rowE[n] = sE; d_curE[n] = sE;
    }
}

__global__ void fill_kernel(const int* __restrict__ srcI,
                            const int* __restrict__ dstI,
                            const float* __restrict__ eattr, int Ei,
                            const int* __restrict__ srcE,
                            const int* __restrict__ dstE,
                            const float* __restrict__ pos, int Ee) {
    int i = blockIdx.x * blockDim.x + threadIdx.x;
    if (i < Ei) {
        int d = dstI[i];
        int slot = atomicAdd(&d_curI[d], 1);
        d_pairI[slot] = make_int2(srcI[i], __float_as_int(eattr[i]));
    }
    if (i < Ee) {
        int s = srcE[i], d = dstE[i];
        int slot = atomicAdd(&d_curE[d], 1);
        float dx = pos[3 * s + 0] - pos[3 * d + 0];
        float dy = pos[3 * s + 1] - pos[3 * d + 1];
        float dz = pos[3 * s + 2] - pos[3 * d + 2];
        float w = expf(-(dx * dx + dy * dy + dz * dz));
        d_pairE[slot] = make_int2(s, __float_as_int(w));
    }
}

// ---------------- fused layer: CSR gather -> dual GEMM -> update ----------------
__device__ __forceinline__ float4 gather_row(const float* __restrict__ h_in,
                                             const int2* __restrict__ pairs,
                                             int s0, int dg, int lane) {
    float4 acc = make_float4(0.f, 0.f, 0.f, 0.f);
    int j = 0;
    for (; j + 4 <= dg; j += 4) {
        int2 p0 = __ldg(&pairs[s0 + j + 0]);
        int2 p1 = __ldg(&pairs[s0 + j + 1]);
        int2 p2 = __ldg(&pairs[s0 + j + 2]);
        int2 p3 = __ldg(&pairs[s0 + j + 3]);
        float4 v0 = __ldg((const float4*)(h_in + (size_t)p0.x * HH) + lane);
        float4 v1 = __ldg((const float4*)(h_in + (size_t)p1.x * HH) + lane);
        float4 v2 = __ldg((const float4*)(h_in + (size_t)p2.x * HH) + lane);
        float4 v3 = __ldg((const float4*)(h_in + (size_t)p3.x * HH) + lane);
        float w0 = __int_as_float(p0.y), w1 = __int_as_float(p1.y);
        float w2 = __int_as_float(p2.y), w3 = __int_as_float(p3.y);
        acc.x = fmaf(v0.x, w0, acc.x); acc.y = fmaf(v0.y, w0, acc.y);
        acc.z = fmaf(v0.z, w0, acc.z); acc.w = fmaf(v0.w, w0, acc.w);
        acc.x = fmaf(v1.x, w1, acc.x); acc.y = fmaf(v1.y, w1, acc.y);
        acc.z = fmaf(v1.z, w1, acc.z); acc.w = fmaf(v1.w, w1, acc.w);
        acc.x = fmaf(v2.x, w2, acc.x); acc.y = fmaf(v2.y, w2, acc.y);
        acc.z = fmaf(v2.z, w2, acc.z); acc.w = fmaf(v2.w, w2, acc.w);
        acc.x = fmaf(v3.x, w3, acc.x); acc.y = fmaf(v3.y, w3, acc.y);
        acc.z = fmaf(v3.z, w3, acc.z); acc.w = fmaf(v3.w, w3, acc.w);
    }
    for (; j < dg; j++) {
        int2 p = __ldg(&pairs[s0 + j]);
        float4 v = __ldg((const float4*)(h_in + (size_t)p.x * HH) + lane);
        float w = __int_as_float(p.y);
        acc.x = fmaf(v.x, w, acc.x); acc.y = fmaf(v.y, w, acc.y);
        acc.z = fmaf(v.z, w, acc.z); acc.w = fmaf(v.w, w, acc.w);
    }
    return acc;
}

__device__ __forceinline__ void gather_tile(const float* __restrict__ h_in,
                                            const int2* __restrict__ pairs,
                                            const int* __restrict__ rowp,
                                            const int* __restrict__ deg,
                                            float* __restrict__ sA,
                                            int n0, int N, int tid) {
    int warp = tid >> 5, lane = tid & 31;
#pragma unroll
    for (int r = 0; r < 8; r++) {
        int row = warp * 8 + r;
        int n = n0 + row;
        float4 acc = make_float4(0.f, 0.f, 0.f, 0.f);
        if (n < N) {
            int s0 = __ldg(&rowp[n]);
            int dg = __ldg(&deg[n]);
            acc = gather_row(h_in, pairs, s0, dg, lane);
        }
        *(float4*)(sA + row * HH + lane * 4) = acc;
    }
}

__device__ __forceinline__ void load_W(const float* __restrict__ Wg,
                                       float* __restrict__ sW, int tid) {
    float4* sWv = (float4*)sW;
    const float4* Wv = (const float4*)Wg;
#pragma unroll
    for (int i = 0; i < 16; i++) sWv[tid + i * 256] = __ldg(&Wv[tid + i * 256]);
}

__device__ __forceinline__ void gemm_tile(const float* __restrict__ sW,
                                          const float* __restrict__ sA,
                                          int r0, int c0, u64 acc[4][4]) {
#pragma unroll 4
    for (int k = 0; k < HH; k += 4) {
        float4 a[4];
#pragma unroll
        for (int r = 0; r < 4; r++)
            a[r] = *(const float4*)(sA + (r0 + r) * HH + k);
#pragma unroll
        for (int kk = 0; kk < 4; kk++) {
            const ulonglong2* wr = (const ulonglong2*)(sW + (k + kk) * HH + c0);
            ulonglong2 wa = wr[0], wb = wr[1];
#pragma unroll
            for (int r = 0; r < 4; r++) {
                float av = (kk == 0) ? a[r].x : (kk == 1) ? a[r].y
                         : (kk == 2) ? a[r].z : a[r].w;
                u64 ap = pack2(av);
                acc[r][0] = fma2(ap, wa.x, acc[r][0]);
                acc[r][1] = fma2(ap, wa.y, acc[r][1]);
                acc[r][2] = fma2(ap, wb.x, acc[r][2]);
                acc[r][3] = fma2(ap, wb.y, acc[r][3]);
            }
        }
    }
}

#define UPD_SMEM_FLOATS (16384 + 8192 + 256)
#define UPD_SMEM_BYTES (UPD_SMEM_FLOATS * 4)

__global__ void __launch_bounds__(256, 2) layer_kernel(
    const float* __restrict__ h_in, float* __restrict__ h_out,
    const float* __restrict__ W1, const float* __restrict__ b1,
    const float* __restrict__ W2, const float* __restrict__ b2, int N) {
    extern __shared__ float sm[];
    float* sW = sm;                 // 16384 floats
    float* sA = sm + 16384;         // 8192 floats
    float* sB1 = sm + 24576;        // 128
    float* sB2 = sm + 24704;        // 128

    int tid = threadIdx.x;          // 256 threads
    int n0 = blockIdx.x * 64;
    if (tid < 128) sB1[tid] = b1[tid];
    else           sB2[tid - 128] = b2[tid - 128];

    const int r0 = (tid >> 4) << 2;       // 16 row groups * 4 rows
    const int c0 = (tid & 15) << 3;       // 16 col groups * 8 cols

    u64 accI[4][4], accE[4][4];
#pragma unroll
    for (int r = 0; r < 4; r++)
#pragma unroll
        for (int p = 0; p < 4; p++) { accI[r][p] = 0ull; accE[r][p] = 0ull; }

    // phase A: intra
    load_W(W1, sW, tid);
    gather_tile(h_in, d_pairI, d_rowI, d_degI, sA, n0, N, tid);
    __syncthreads();
    gemm_tile(sW, sA, r0, c0, accI);
    __syncthreads();
    // phase B: inter
    load_W(W2, sW, tid);
    gather_tile(h_in, d_pairE, d_rowE, d_degE, sA, n0, N, tid);
    __syncthreads();
    gemm_tile(sW, sA, r0, c0, accE);

    // epilogue
#pragma unroll
    for (int r = 0; r < 4; r++) {
        int n = n0 + r0 + r;
        if (n >= N) break;
        float ci = (float)__ldg(&d_degI[n]);
        float ce = (float)__ldg(&d_degE[n]);
        float inv = 1.0f / (ci + 1.0f);
        float ld = logf(ce + 1.0f);
        long long base = (long long)n * HH + c0;
#pragma unroll
        for (int p = 0; p < 4; p++) {
            float2 mi = unpack2(accI[r][p]);
            float2 me = unpack2(accE[r][p]);
            int c = c0 + 2 * p;
            mi.x = (mi.x + ci * sB1[c])     * inv;
            mi.y = (mi.y + ci * sB1[c + 1]) * inv;
            me.x = (me.x + ce * sB2[c])     * ld;
            me.y = (me.y + ce * sB2[c + 1]) * ld;
            float2 vp = *(float2*)(d_vp + base + 2 * p);
            float2 vl = *(float2*)(d_vl + base + 2 * p);
            float2 hh = *(const float2*)(h_in + base + 2 * p);
            float nvp0 = silu_f(mi.x + vp.x), nvp1 = silu_f(mi.y + vp.y);
            float nvl0 = silu_f(me.x + vl.x), nvl1 = silu_f(me.y + vl.y);
            hh.x += nvp0 + nvl0;
            hh.y += nvp1 + nvl1;
            *(float2*)(d_vp + base + 2 * p) = make_float2(nvp0, nvp1);
            *(float2*)(d_vl + base + 2 * p) = make_float2(nvl0, nvl1);
            *(float2*)(h_out + base + 2 * p) = hh;
        }
    }
}

// ---------------- global_add_pool (batch is sorted) ----------------
__global__ void pool_kernel(const float* __restrict__ h,
                            const int* __restrict__ batch, int N) {
    const int NPB = 512;
    __shared__ int sbatch[NPB];
    int n0 = blockIdx.x * NPB;
    int tid = threadIdx.x;            // 128 threads (one per column)
    int cnt = min(NPB, N - n0);
    for (int i = tid; i < cnt; i += 128) sbatch[i] = batch[n0 + i];
    __syncthreads();
    float acc = 0.0f;
    int cur = sbatch[0];
    for (int i = 0; i < cnt; i++) {
        int g = sbatch[i];
        if (g != cur) {
            atomicAdd(&d_gpool[cur * HH + tid], acc);
            acc = 0.0f;
            cur = g;
        }
        acc += h[(long long)(n0 + i) * HH + tid];
    }
    atomicAdd(&d_gpool[cur * HH + tid], acc);
}

// ---------------- FC head (one block per graph) ----------------
__global__ void head_kernel(const float* __restrict__ fcW,
                            const float* __restrict__ fcb,
                            const float* __restrict__ gam,
                            const float* __restrict__ bet,
                            const float* __restrict__ outW,
                            const float* __restrict__ outb,
                            float* __restrict__ out) {
    int gr = blockIdx.x;
    int c = threadIdx.x;              // 128 threads
    __shared__ float sg[HH];
    __shared__ float red[4];
    sg[c] = d_gpool[gr * HH + c];
    __syncthreads();
    const float bns = 1.0f / sqrtf(1.0f + 1e-5f);
    for (int j = 0; j < 3; j++) {
        const float* Wj = fcW + j * HH * HH;
        float acc = fcb[j * HH + c];
#pragma unroll 8
        for (int k = 0; k < HH; k++) acc += sg[k] * Wj[k * HH + c];
        acc = acc > 0.0f ? acc : 0.01f * acc;           // leaky_relu
        acc = acc * bns * gam[j * HH + c] + bet[j * HH + c];
        __syncthreads();
        sg[c] = acc;
        __syncthreads();
    }
    float v = sg[c] * outW[c];
#pragma unroll
    for (int o = 16; o > 0; o >>= 1) v += __shfl_xor_sync(0xffffffffu, v, o);
    if ((c & 31) == 0) red[c >> 5] = v;
    __syncthreads();
    if (c == 0) out[gr] = red[0] + red[1] + red[2] + red[3] + outb[0];
}

// ---------------- launch ----------------
extern "C" void kernel_launch(void* const* d_in, const int* in_sizes, int n_in,
                              void* d_out, int out_size) {
    const float* x     = (const float*)d_in[0];
    const int*   eii   = (const int*)d_in[1];
    const int*   eie   = (const int*)d_in[2];
    const float* pos   = (const float*)d_in[3];
    const float* eattr = (const float*)d_in[4];
    const int*   batch = (const int*)d_in[5];
    const float* linW  = (const float*)d_in[6];
    const float* linb  = (const float*)d_in[7];
    const float* Wi    = (const float*)d_in[8];
    const float* bi    = (const float*)d_in[9];
    const float* We    = (const float*)d_in[10];
    const float* be    = (const float*)d_in[11];
    const float* fcW   = (const float*)d_in[12];
    const float* fcb   = (const float*)d_in[13];
    const float* gam   = (const float*)d_in[14];
    const float* bet   = (const float*)d_in[15];
    const float* outW  = (const float*)d_in[16];
    const float* outb  = (const float*)d_in[17];
    float* out = (float*)d_out;

    int N  = in_sizes[5];
    int Ei = in_sizes[4];        // edge_attr has E_INTRA elements
    int Ee = in_sizes[2] / 2;

    const int* srcI = eii;
    const int* dstI = eii + Ei;
    const int* srcE = eie;
    const int* dstE = eie + Ee;

    cudaFuncSetAttribute(layer_kernel,
                         cudaFuncAttributeMaxDynamicSharedMemorySize,
                         UPD_SMEM_BYTES);

    zero_kernel<<<(NN * HH / 4 + 255) / 256, 256>>>();
    embed_kernel<<<(N + 63) / 64, 128>>>(x, linW, linb, N);

    int Emax = Ei > Ee ? Ei : Ee;
    count_kernel<<<(Emax + 255) / 256, 256>>>(dstI, Ei, dstE, Ee);
    alloc_kernel<<<(N + 255) / 256, 256>>>(N);
    fill_kernel<<<(Emax + 255) / 256, 256>>>(srcI, dstI, eattr, Ei,
                                             srcE, dstE, pos, Ee);

    float* hbuf[2] = { d_h0, d_h1 };
    // resolve device symbol addresses is not allowed at capture time via API;
    // use a small trampoline: pass via kernel pointer arguments using the
    // __device__ arrays directly through a helper kernel is unnecessary —
    // we can take their addresses in device code only. Instead, ping-pong
    // by passing symbol-derived pointers obtained statically:
    // (cudaGetSymbolAddress is host API, allowed outside capture rules? It is
    //  not a stream op; but to stay safe we hard-wire via launches below.)
    (void)hbuf;

    for (int l = 0; l < 4; l++) {
        // even layers: h0 -> h1, odd layers: h1 -> h0
        // device-symbol pointers are resolved inside a tiny wrapper below.
        extern __global__ void layer_wrap(int even, const float*, const float*,
                                          const float*, const float*, int);
        // (fallthrough — actual launch below)
        break;
    }

    // Direct launches with symbol addresses taken via device lambdas are not
    // possible from host; instead use cudaGetSymbolAddress once per call
    // (host-side API, not a memory allocation, not a stream operation).
    static float* p_h0 = nullptr;
    static float* p_h1 = nullptr;
    if (!p_h0) {
        cudaGetSymbolAddress((void**)&p_h0, d_h0);
        cudaGetSymbolAddress((void**)&p_h1, d_h1);
    }

    for (int l = 0; l < 4; l++) {
        const float* hin  = (l & 1) ? p_h1 : p_h0;
        float*       hout = (l & 1) ? p_h0 : p_h1;
        layer_kernel<<<(N + 63) / 64, 256, UPD_SMEM_BYTES>>>(
            hin, hout,
            Wi + (size_t)l * HH * HH, bi + (size_t)l * HH,
            We + (size_t)l * HH * HH, be + (size_t)l * HH, N);
    }

    pool_kernel<<<(N + 511) / 512, 128>>>(p_h0, batch, N);
    head_kernel<<<GG, 128>>>(fcW, fcb, gam, bet, outW, outb, out);
}